// round 12
// baseline (speedup 1.0000x reference)
#include <cuda_runtime.h>
#include <cstdint>

// Problem constants (shape-fixed per problem instance)
#define DD    128
#define NMAX  50000
#define EMAX  800000
// GEMM2 (128-row) smem: W 64KB + X 64KB
#define GEMM_SMEM_BYTES  (32768 * 4)
// fused gather-GEMM (64-row): W 64KB + X 32KB
#define GG_SMEM_BYTES    (24576 * 4)

// -------- scratch (allocation-free: __device__ globals) --------
__device__ float g_bufs[2ull * NMAX * DD];  // h, xraw
// [0:128) colsum  [128:256) colsumsq  [256:384) bn scale  [384:512) bn shift
__device__ __align__(16) float g_small[512];
__device__ int g_edge64;
// CSR scratch
__device__ int g_sorted_src[EMAX];
__device__ int g_rowoff[NMAX + 1];   // becomes END offsets after placement
__device__ int g_counts[NMAX];
__device__ int g_partials[1024];

// -------- setup: zero counts + zero stats + parallel dtype detect --------
__global__ void setup_kernel(const int* __restrict__ ei, int n) {
    int i = blockIdx.x * 256 + threadIdx.x;
    if (i < n) g_counts[i] = 0;
    if (blockIdx.x == 0) {
        int t = threadIdx.x;
        g_small[t] = 0.0f;               // zero colsum + colsumsq (t<256)
        __shared__ int ok;
        if (t == 0) ok = 1;
        __syncthreads();
        if (ei[2 * t + 1] != 0) atomicExch(&ok, 0);
        __syncthreads();
        if (t == 0) g_edge64 = ok;
    }
}

// ---- counting sort of edges by dst (built once per launch) ----
__global__ void hist_kernel(const void* __restrict__ ei, int E) {
    int base = blockIdx.x * blockDim.x + threadIdx.x;
    int stride = gridDim.x * blockDim.x;
    if (g_edge64) {
        const long long* dstp = (const long long*)ei + E;
        for (int e = base; e < E; e += stride)
            atomicAdd(&g_counts[(int)dstp[e]], 1);
    } else {
        const int* dstp = (const int*)ei + E;
        for (int e = base; e < E; e += stride)
            atomicAdd(&g_counts[dstp[e]], 1);
    }
}

__global__ void scanA_kernel(int n) {
    __shared__ int sm[256];
    int t = threadIdx.x;
    int i = blockIdx.x * 256 + t;
    int v = (i < n) ? g_counts[i] : 0;
    sm[t] = v;
    __syncthreads();
#pragma unroll
    for (int off = 1; off < 256; off <<= 1) {
        int add = (t >= off) ? sm[t - off] : 0;
        __syncthreads();
        sm[t] += add;
        __syncthreads();
    }
    if (i < n) g_rowoff[i] = sm[t] - v;
    if (t == 255) g_partials[blockIdx.x] = sm[t];
}

// exclusive scan of block partials (nb <= 256), single block of 256
__global__ void scanB_kernel(int nb) {
    __shared__ int sm[256];
    int t = threadIdx.x;
    int v = (t < nb) ? g_partials[t] : 0;
    sm[t] = v;
    __syncthreads();
#pragma unroll
    for (int off = 1; off < 256; off <<= 1) {
        int add = (t >= off) ? sm[t - off] : 0;
        __syncthreads();
        sm[t] += add;
        __syncthreads();
    }
    if (t < nb) g_partials[t] = sm[t] - v;
}

__global__ void scanC2_kernel(int n) {
    int i = blockIdx.x * 256 + threadIdx.x;
    if (i < n) g_rowoff[i] += g_partials[blockIdx.x];
}

__global__ void place_kernel(const void* __restrict__ ei, int E) {
    int base = blockIdx.x * blockDim.x + threadIdx.x;
    int stride = gridDim.x * blockDim.x;
    if (g_edge64) {
        const long long* e64 = (const long long*)ei;
        for (int e = base; e < E; e += stride) {
            int s = (int)e64[e];
            int d = (int)e64[E + e];
            g_sorted_src[atomicAdd(&g_rowoff[d], 1)] = s;
        }
    } else {
        const int* e32 = (const int*)ei;
        for (int e = base; e < E; e += stride) {
            int s = e32[e];
            int d = e32[E + e];
            g_sorted_src[atomicAdd(&g_rowoff[d], 1)] = s;
        }
    }
}

// ================== fused gather + GEMM1 ==================
// out[n,128] = [ (1+eps)*act(raw[i]) + sum_{j in N(i)} act(raw[j]) ] @ W + bias
// act = BN(scale/shift from g_small)+ReLU when applyBN, else identity.
// 64-row tile, 256 threads, 2 CTAs/SM for gather<->FMA cross-CTA overlap.
// Always accumulates per-column stats of the output into g_small.
__global__ __launch_bounds__(256, 2)
void gg_kernel(const float* __restrict__ raw,
               const float* __restrict__ W,
               const float* __restrict__ bias,
               float* __restrict__ out,
               const float* __restrict__ epsArr,
               int layer, int n, int applyBN) {
    extern __shared__ float smem[];
    float* ws = smem;              // [128][128] W (k x c)
    float* xs = smem + 16384;      // [64][128]  A tile
    float4* ws4 = (float4*)ws;
    float4* xs4 = (float4*)xs;

    int tid = threadIdx.x;
    int warp = tid >> 5;
    int lane = tid & 31;
    int rowBase = blockIdx.x << 6;

    // load W (4096 float4)
    const float4* W4 = (const float4*)W;
#pragma unroll
    for (int i = 0; i < 16; i++) ws4[tid + 256 * i] = W4[tid + 256 * i];

    // gather A tile: warp w handles rows w*8 .. w*8+7
    {
        const float4* X4 = (const float4*)raw;
        float e1 = 1.0f + epsArr[layer];
        float4 s = make_float4(1.f, 1.f, 1.f, 1.f);
        float4 t = make_float4(0.f, 0.f, 0.f, 0.f);
        if (applyBN) {
            s = ((const float4*)(g_small + 256))[lane];
            t = ((const float4*)(g_small + 384))[lane];
        }
#pragma unroll 1
        for (int r8 = 0; r8 < 8; r8++) {
            int lrow = warp * 8 + r8;
            int node = rowBase + lrow;
            float ax = 0.f, ay = 0.f, az = 0.f, aw = 0.f;
            if (node < n) {
                float4 v = X4[(size_t)node * 32 + lane];
                if (applyBN) {
                    v.x = fmaxf(fmaf(v.x, s.x, t.x), 0.0f);
                    v.y = fmaxf(fmaf(v.y, s.y, t.y), 0.0f);
                    v.z = fmaxf(fmaf(v.z, s.z, t.z), 0.0f);
                    v.w = fmaxf(fmaf(v.w, s.w, t.w), 0.0f);
                }
                ax = v.x * e1; ay = v.y * e1; az = v.z * e1; aw = v.w * e1;
                int e = (node == 0) ? 0 : g_rowoff[node - 1];
                int end = g_rowoff[node];
                for (; e + 4 <= end; e += 4) {
                    int s0 = g_sorted_src[e];
                    int s1 = g_sorted_src[e + 1];
                    int s2 = g_sorted_src[e + 2];
                    int s3 = g_sorted_src[e + 3];
                    float4 v0 = X4[(size_t)s0 * 32 + lane];
                    float4 v1 = X4[(size_t)s1 * 32 + lane];
                    float4 v2 = X4[(size_t)s2 * 32 + lane];
                    float4 v3 = X4[(size_t)s3 * 32 + lane];
                    if (applyBN) {
                        v0.x = fmaxf(fmaf(v0.x, s.x, t.x), 0.0f);
                        v0.y = fmaxf(fmaf(v0.y, s.y, t.y), 0.0f);
                        v0.z = fmaxf(fmaf(v0.z, s.z, t.z), 0.0f);
                        v0.w = fmaxf(fmaf(v0.w, s.w, t.w), 0.0f);
                        v1.x = fmaxf(fmaf(v1.x, s.x, t.x), 0.0f);
                        v1.y = fmaxf(fmaf(v1.y, s.y, t.y), 0.0f);
                        v1.z = fmaxf(fmaf(v1.z, s.z, t.z), 0.0f);
                        v1.w = fmaxf(fmaf(v1.w, s.w, t.w), 0.0f);
                        v2.x = fmaxf(fmaf(v2.x, s.x, t.x), 0.0f);
                        v2.y = fmaxf(fmaf(v2.y, s.y, t.y), 0.0f);
                        v2.z = fmaxf(fmaf(v2.z, s.z, t.z), 0.0f);
                        v2.w = fmaxf(fmaf(v2.w, s.w, t.w), 0.0f);
                        v3.x = fmaxf(fmaf(v3.x, s.x, t.x), 0.0f);
                        v3.y = fmaxf(fmaf(v3.y, s.y, t.y), 0.0f);
                        v3.z = fmaxf(fmaf(v3.z, s.z, t.z), 0.0f);
                        v3.w = fmaxf(fmaf(v3.w, s.w, t.w), 0.0f);
                    }
                    ax += v0.x + v1.x + v2.x + v3.x;
                    ay += v0.y + v1.y + v2.y + v3.y;
                    az += v0.z + v1.z + v2.z + v3.z;
                    aw += v0.w + v1.w + v2.w + v3.w;
                }
                for (; e < end; e++) {
                    float4 v0 = X4[(size_t)g_sorted_src[e] * 32 + lane];
                    if (applyBN) {
                        v0.x = fmaxf(fmaf(v0.x, s.x, t.x), 0.0f);
                        v0.y = fmaxf(fmaf(v0.y, s.y, t.y), 0.0f);
                        v0.z = fmaxf(fmaf(v0.z, s.z, t.z), 0.0f);
                        v0.w = fmaxf(fmaf(v0.w, s.w, t.w), 0.0f);
                    }
                    ax += v0.x; ay += v0.y; az += v0.z; aw += v0.w;
                }
            }
            xs4[lrow * 32 + lane] = make_float4(ax, ay, az, aw);
        }
    }
    __syncthreads();

    // GEMM: 64x128 tile; thread = 4 rows x 8 cols
    int tx = tid & 15;             // col groups 4tx.. and 64+4tx..
    int ty = tid >> 4;             // row group: rows 4ty..4ty+3
    unsigned long long acc2[4][4];
#pragma unroll
    for (int r = 0; r < 4; r++)
#pragma unroll
        for (int c = 0; c < 4; c++) acc2[r][c] = 0ull;

#pragma unroll 2
    for (int k = 0; k < 128; k += 4) {
        float a[4][4];
#pragma unroll
        for (int r = 0; r < 4; r++) {
            float4 av = xs4[(ty * 4 + r) * 32 + (k >> 2)];
            a[r][0] = av.x; a[r][1] = av.y; a[r][2] = av.z; a[r][3] = av.w;
        }
#pragma unroll
        for (int kk = 0; kk < 4; kk++) {
            float4 w0 = ws4[(k + kk) * 32 + tx];
            float4 w1 = ws4[(k + kk) * 32 + tx + 16];
            unsigned long long w2[4];
            asm("mov.b64 %0, {%1, %2};" : "=l"(w2[0]) : "f"(w0.x), "f"(w0.y));
            asm("mov.b64 %0, {%1, %2};" : "=l"(w2[1]) : "f"(w0.z), "f"(w0.w));
            asm("mov.b64 %0, {%1, %2};" : "=l"(w2[2]) : "f"(w1.x), "f"(w1.y));
            asm("mov.b64 %0, {%1, %2};" : "=l"(w2[3]) : "f"(w1.z), "f"(w1.w));
#pragma unroll
            for (int r = 0; r < 4; r++) {
                unsigned long long a2;
                asm("mov.b64 %0, {%1, %1};" : "=l"(a2) : "f"(a[r][kk]));
#pragma unroll
                for (int c = 0; c < 4; c++)
                    asm("fma.rn.f32x2 %0, %1, %2, %0;"
                        : "+l"(acc2[r][c]) : "l"(a2), "l"(w2[c]));
            }
        }
    }

    float4 b0 = ((const float4*)bias)[tx];
    float4 b1v = ((const float4*)bias)[tx + 16];
    float bv[8] = {b0.x, b0.y, b0.z, b0.w, b1v.x, b1v.y, b1v.z, b1v.w};

    float psum[8], psq[8];
#pragma unroll
    for (int c = 0; c < 8; c++) { psum[c] = 0.0f; psq[c] = 0.0f; }

#pragma unroll
    for (int r = 0; r < 4; r++) {
        int grow = rowBase + ty * 4 + r;
        if (grow < n) {
            float o[8];
#pragma unroll
            for (int c = 0; c < 4; c++) {
                float lo, hi;
                asm("mov.b64 {%0, %1}, %2;" : "=f"(lo), "=f"(hi) : "l"(acc2[r][c]));
                o[2 * c] = lo + bv[2 * c];
                o[2 * c + 1] = hi + bv[2 * c + 1];
            }
            ((float4*)out)[(size_t)grow * 32 + tx] = make_float4(o[0], o[1], o[2], o[3]);
            ((float4*)out)[(size_t)grow * 32 + tx + 16] = make_float4(o[4], o[5], o[6], o[7]);
#pragma unroll
            for (int c = 0; c < 8; c++) {
                psum[c] += o[c];
                psq[c] += o[c] * o[c];
            }
        }
    }

    // stats reduce (reuse ws as scratch)
    __syncthreads();
    {
        float* redS = ws;              // [16][128]
        float* redQ = ws + 2048;
        ((float4*)&redS[ty * 128])[tx]      = make_float4(psum[0], psum[1], psum[2], psum[3]);
        ((float4*)&redS[ty * 128])[tx + 16] = make_float4(psum[4], psum[5], psum[6], psum[7]);
        ((float4*)&redQ[ty * 128])[tx]      = make_float4(psq[0], psq[1], psq[2], psq[3]);
        ((float4*)&redQ[ty * 128])[tx + 16] = make_float4(psq[4], psq[5], psq[6], psq[7]);
        __syncthreads();
        if (tid < 128) {
            float sv = 0.0f;
#pragma unroll
            for (int t = 0; t < 16; t++) sv += redS[t * 128 + tid];
            atomicAdd(&g_small[tid], sv);
        } else {
            int c = tid - 128;
            float q = 0.0f;
#pragma unroll
            for (int t = 0; t < 16; t++) q += redQ[t * 128 + c];
            atomicAdd(&g_small[128 + c], q);
        }
    }
}

// ================== GEMM2 (128-row tile, as R9) ==================
__global__ __launch_bounds__(256, 1)
void gemm_kernel(const float* __restrict__ A,
                 const float* __restrict__ W,
                 const float* __restrict__ bias,
                 float* __restrict__ out,
                 int n, int applyBN, int accumStats) {
    extern __shared__ float smem[];
    float* ws = smem;
    float* xs = smem + 16384;
    float4* ws4 = (float4*)ws;
    float4* xs4 = (float4*)xs;

    int tid = threadIdx.x;
    int tx = tid & 15;
    int ty = tid >> 4;
    int rowBase = blockIdx.x << 7;

    const float4* W4 = (const float4*)W;
#pragma unroll
    for (int i = 0; i < 16; i++) ws4[tid + 256 * i] = W4[tid + 256 * i];

    const float4* A4 = (const float4*)A;
#pragma unroll
    for (int i = 0; i < 16; i++) {
        int li = tid + 256 * i;
        int r = li >> 5;
        int c4 = li & 31;
        int grow = rowBase + r;
        float4 v = make_float4(0.f, 0.f, 0.f, 0.f);
        if (grow < n) v = A4[(size_t)grow * 32 + c4];
        if (applyBN) {
            float4 s = ((const float4*)(g_small + 256))[c4];
            float4 t = ((const float4*)(g_small + 384))[c4];
            v.x = fmaxf(fmaf(v.x, s.x, t.x), 0.0f);
            v.y = fmaxf(fmaf(v.y, s.y, t.y), 0.0f);
            v.z = fmaxf(fmaf(v.z, s.z, t.z), 0.0f);
            v.w = fmaxf(fmaf(v.w, s.w, t.w), 0.0f);
        }
        xs4[li] = v;
    }
    __syncthreads();

    unsigned long long acc2[8][4];
#pragma unroll
    for (int r = 0; r < 8; r++)
#pragma unroll
        for (int c = 0; c < 4; c++) acc2[r][c] = 0ull;

#pragma unroll 2
    for (int k = 0; k < 128; k += 4) {
        float a[8][4];
#pragma unroll
        for (int r = 0; r < 8; r++) {
            float4 av = xs4[(ty * 8 + r) * 32 + (k >> 2)];
            a[r][0] = av.x; a[r][1] = av.y; a[r][2] = av.z; a[r][3] = av.w;
        }
#pragma unroll
        for (int kk = 0; kk < 4; kk++) {
            float4 w0 = ws4[(k + kk) * 32 + tx];
            float4 w1 = ws4[(k + kk) * 32 + tx + 16];
            unsigned long long w2[4];
            asm("mov.b64 %0, {%1, %2};" : "=l"(w2[0]) : "f"(w0.x), "f"(w0.y));
            asm("mov.b64 %0, {%1, %2};" : "=l"(w2[1]) : "f"(w0.z), "f"(w0.w));
            asm("mov.b64 %0, {%1, %2};" : "=l"(w2[2]) : "f"(w1.x), "f"(w1.y));
            asm("mov.b64 %0, {%1, %2};" : "=l"(w2[3]) : "f"(w1.z), "f"(w1.w));
#pragma unroll
            for (int r = 0; r < 8; r++) {
                unsigned long long a2;
                asm("mov.b64 %0, {%1, %1};" : "=l"(a2) : "f"(a[r][kk]));
#pragma unroll
                for (int c = 0; c < 4; c++)
                    asm("fma.rn.f32x2 %0, %1, %2, %0;"
                        : "+l"(acc2[r][c]) : "l"(a2), "l"(w2[c]));
            }
        }
    }

    float4 b0 = ((const float4*)bias)[tx];
    float4 b1v = ((const float4*)bias)[tx + 16];
    float bv[8] = {b0.x, b0.y, b0.z, b0.w, b1v.x, b1v.y, b1v.z, b1v.w};

    float psum[8], psq[8];
#pragma unroll
    for (int c = 0; c < 8; c++) { psum[c] = 0.0f; psq[c] = 0.0f; }

#pragma unroll
    for (int r = 0; r < 8; r++) {
        int grow = rowBase + ty * 8 + r;
        if (grow < n) {
            float o[8];
#pragma unroll
            for (int c = 0; c < 4; c++) {
                float lo, hi;
                asm("mov.b64 {%0, %1}, %2;" : "=f"(lo), "=f"(hi) : "l"(acc2[r][c]));
                o[2 * c] = lo + bv[2 * c];
                o[2 * c + 1] = hi + bv[2 * c + 1];
            }
            ((float4*)out)[(size_t)grow * 32 + tx] = make_float4(o[0], o[1], o[2], o[3]);
            ((float4*)out)[(size_t)grow * 32 + tx + 16] = make_float4(o[4], o[5], o[6], o[7]);
            if (accumStats) {
#pragma unroll
                for (int c = 0; c < 8; c++) {
                    psum[c] += o[c];
                    psq[c] += o[c] * o[c];
                }
            }
        }
    }

    if (accumStats) {
        __syncthreads();
        float* redS = ws;
        float* redQ = ws + 2048;
        ((float4*)&redS[ty * 128])[tx]      = make_float4(psum[0], psum[1], psum[2], psum[3]);
        ((float4*)&redS[ty * 128])[tx + 16] = make_float4(psum[4], psum[5], psum[6], psum[7]);
        ((float4*)&redQ[ty * 128])[tx]      = make_float4(psq[0], psq[1], psq[2], psq[3]);
        ((float4*)&redQ[ty * 128])[tx + 16] = make_float4(psq[4], psq[5], psq[6], psq[7]);
        __syncthreads();
        if (tid < 128) {
            float sv = 0.0f;
#pragma unroll
            for (int t = 0; t < 16; t++) sv += redS[t * 128 + tid];
            atomicAdd(&g_small[tid], sv);
        } else {
            int c = tid - 128;
            float q = 0.0f;
#pragma unroll
            for (int t = 0; t < 16; t++) q += redQ[t * 128 + c];
            atomicAdd(&g_small[128 + c], q);
        }
    }
}

__global__ void bnparams_kernel(const float* __restrict__ gamma,
                                const float* __restrict__ beta,
                                float invN) {
    int c = threadIdx.x;
    float mean = g_small[c] * invN;
    float var = g_small[128 + c] * invN - mean * mean;
    float sc = gamma[c] * rsqrtf(fmaxf(var, 0.0f) + 1e-5f);
    g_small[256 + c] = sc;
    g_small[384 + c] = beta[c] - mean * sc;
    g_small[c] = 0.0f;
    g_small[128 + c] = 0.0f;
}

extern "C" void kernel_launch(void* const* d_in, const int* in_sizes, int n_in,
                              void* d_out, int out_size) {
    const float* x     = (const float*)d_in[0];
    const void*  ei    = d_in[1];
    const float* eps   = (const float*)d_in[2];
    const float* W1    = (const float*)d_in[3];
    const float* b1    = (const float*)d_in[4];
    const float* g1    = (const float*)d_in[5];
    const float* beta1 = (const float*)d_in[6];
    const float* W2    = (const float*)d_in[7];
    const float* b2    = (const float*)d_in[8];
    const float* bng   = (const float*)d_in[9];
    const float* bnb   = (const float*)d_in[10];
    float* out = (float*)d_out;

    int n = in_sizes[0] / DD;
    int E = in_sizes[1] / 2;

    float* bufs = nullptr;
    cudaGetSymbolAddress((void**)&bufs, g_bufs);
    float* h    = bufs;
    float* xraw = bufs + (size_t)1 * NMAX * DD;

    cudaFuncSetAttribute((const void*)gemm_kernel,
                         cudaFuncAttributeMaxDynamicSharedMemorySize, GEMM_SMEM_BYTES);
    cudaFuncSetAttribute((const void*)gg_kernel,
                         cudaFuncAttributeMaxDynamicSharedMemorySize, GG_SMEM_BYTES);

    int nb256 = (n + 255) / 256;
    int edgeBlocks = (E + 8 * 256 - 1) / (8 * 256);

    setup_kernel<<<nb256, 256>>>((const int*)ei, n);
    hist_kernel<<<edgeBlocks, 256>>>(ei, E);
    scanA_kernel<<<nb256, 256>>>(n);
    scanB_kernel<<<1, 256>>>(nb256);
    scanC2_kernel<<<nb256, 256>>>(n);
    place_kernel<<<edgeBlocks, 256>>>(ei, E);

    int ggBlocks = (n + 63) / 64;
    int gemmBlocks = (n + 127) / 128;
    float invN = 1.0f / (float)n;

    for (int layer = 0; layer < 3; layer++) {
        const float* raw = (layer == 0) ? x : xraw;
        // fused: BN(prev)+ReLU applied at gather; GIN agg; GEMM1; stats
        gg_kernel<<<ggBlocks, 256, GG_SMEM_BYTES>>>(
            raw, W1 + (size_t)layer * DD * DD, b1 + layer * DD, h,
            eps, layer, n, (layer > 0) ? 1 : 0);
        bnparams_kernel<<<1, 128>>>(g1 + layer * DD, beta1 + layer * DD, invN);
        int last = (layer == 2);
        float* o = last ? out : xraw;
        gemm_kernel<<<gemmBlocks, 256, GEMM_SMEM_BYTES>>>(
            h, W2 + (size_t)layer * DD * DD, b2 + layer * DD, o, n, 1, last ? 0 : 1);
        if (!last)
            bnparams_kernel<<<1, 128>>>(bng + layer * DD, bnb + layer * DD, invN);
    }
}

// round 13
// speedup vs baseline: 1.1335x; 1.1335x over previous
#include <cuda_runtime.h>
#include <cstdint>

// Problem constants (shape-fixed per problem instance)
#define DD    128
#define NMAX  50000
#define EMAX  800000
#define GEMM_SMEM_BYTES  (32768 * 4)

// -------- scratch (allocation-free: __device__ globals) --------
__device__ float g_bufs[4ull * NMAX * DD];  // xn, agg, h, xraw
// per-layer stats slots: [slot][0:128)=colsum [128:256)=colsumsq
__device__ __align__(16) float g_stats[6][256];
__device__ int g_edge64;
// CSR scratch
__device__ int g_sorted_src[EMAX];
__device__ int g_rowoff[NMAX + 1];   // exclusive offsets; becomes END after place
__device__ int g_counts[NMAX];
__device__ unsigned int g_scanstat[256];

#define SFLAG_AGG 0x40000000u
#define SFLAG_PRE 0x80000000u
#define SVAL      0x3FFFFFFFu

// -------- setup: zero counts/stats/scanstat + parallel dtype detect --------
__global__ void setup_kernel(const int* __restrict__ ei, int n) {
    int b = blockIdx.x, t = threadIdx.x;
    int i = b * 256 + t;
    if (i < n) g_counts[i] = 0;
    if (b < 6) ((float*)g_stats)[b * 256 + t] = 0.0f;
    if (b == 6) g_scanstat[t] = 0u;
    if (b == 7) {
        __shared__ int ok;
        if (t == 0) ok = 1;
        __syncthreads();
        // int64 node ids < 2^31 -> every odd int32 word is zero
        if (ei[2 * t + 1] != 0) atomicExch(&ok, 0);
        __syncthreads();
        if (t == 0) g_edge64 = ok;
    }
}

// ---- counting sort of edges by dst (built once per launch) ----
__global__ void hist_kernel(const void* __restrict__ ei, int E) {
    int base = blockIdx.x * blockDim.x + threadIdx.x;
    int stride = gridDim.x * blockDim.x;
    if (g_edge64) {
        const long long* dstp = (const long long*)ei + E;
        for (int e = base; e < E; e += stride)
            atomicAdd(&g_counts[(int)dstp[e]], 1);
    } else {
        const int* dstp = (const int*)ei + E;
        for (int e = base; e < E; e += stride)
            atomicAdd(&g_counts[dstp[e]], 1);
    }
}

// single-pass exclusive scan of counts -> g_rowoff (decoupled lookback)
__global__ void scan_kernel(int n) {
    __shared__ int sm[256];
    __shared__ int s_base;
    int t = threadIdx.x, b = blockIdx.x;
    int i = b * 256 + t;
    int v = (i < n) ? g_counts[i] : 0;
    sm[t] = v;
    __syncthreads();
#pragma unroll
    for (int off = 1; off < 256; off <<= 1) {
        int add = (t >= off) ? sm[t - off] : 0;
        __syncthreads();
        sm[t] += add;
        __syncthreads();
    }
    int incl = sm[t];
    int total = sm[255];
    if (t == 0) {
        if (b == 0) {
            atomicExch(&g_scanstat[0], SFLAG_PRE | (unsigned)total);
            s_base = 0;
        } else {
            atomicExch(&g_scanstat[b], SFLAG_AGG | (unsigned)total);
            unsigned sum = 0;
            int p = b - 1;
            while (true) {
                unsigned w = atomicOr(&g_scanstat[p], 0u);   // read
                if (w & SFLAG_PRE) { sum += w & SVAL; break; }
                if (w & SFLAG_AGG) { sum += w & SVAL; p--; }
            }
            atomicExch(&g_scanstat[b], SFLAG_PRE | (sum + (unsigned)total));
            s_base = (int)sum;
        }
    }
    __syncthreads();
    if (i < n) g_rowoff[i] = s_base + incl - v;   // exclusive
}

// place edges: rowoff cursor -> END offsets afterwards
__global__ void place_kernel(const void* __restrict__ ei, int E) {
    int base = blockIdx.x * blockDim.x + threadIdx.x;
    int stride = gridDim.x * blockDim.x;
    if (g_edge64) {
        const long long* e64 = (const long long*)ei;
        for (int e = base; e < E; e += stride) {
            int s = (int)e64[e];
            int d = (int)e64[E + e];
            g_sorted_src[atomicAdd(&g_rowoff[d], 1)] = s;
        }
    } else {
        const int* e32 = (const int*)ei;
        for (int e = base; e < E; e += stride) {
            int s = e32[e];
            int d = e32[E + e];
            g_sorted_src[atomicAdd(&g_rowoff[d], 1)] = s;
        }
    }
}

// prep: xn = BN+ReLU(raw); BN params computed inline from stats slot
__global__ void prep_kernel(const float* __restrict__ raw,
                            float* __restrict__ xn,
                            const float* __restrict__ statsIn,
                            const float* __restrict__ gamma,
                            const float* __restrict__ beta,
                            float invN, int n) {
    __shared__ __align__(16) float bnsc[128], bnsh[128];
    int tid = threadIdx.x;
    if (tid < 128) {
        float mean = statsIn[tid] * invN;
        float var = statsIn[128 + tid] * invN - mean * mean;
        float scv = gamma[tid] * rsqrtf(fmaxf(var, 0.0f) + 1e-5f);
        bnsc[tid] = scv;
        bnsh[tid] = beta[tid] - mean * scv;
    }
    __syncthreads();
    int idx = blockIdx.x * blockDim.x + tid;
    int total = n * (DD / 4);
    if (idx >= total) return;
    float4 v = ((const float4*)raw)[idx];
    int c4 = idx & 31;
    float4 s = ((const float4*)bnsc)[c4];
    float4 t = ((const float4*)bnsh)[c4];
    v.x = fmaxf(fmaf(v.x, s.x, t.x), 0.0f);
    v.y = fmaxf(fmaf(v.y, s.y, t.y), 0.0f);
    v.z = fmaxf(fmaf(v.z, s.z, t.z), 0.0f);
    v.w = fmaxf(fmaf(v.w, s.w, t.w), 0.0f);
    ((float4*)xn)[idx] = v;
}

// gather aggregation: one warp per dst node.
__global__ void agg_kernel(const float* __restrict__ xn,
                           float* __restrict__ agg,
                           const float* __restrict__ epsArr,
                           int layer, int n) {
    int node = (blockIdx.x * blockDim.x + threadIdx.x) >> 5;
    int lane = threadIdx.x & 31;
    if (node >= n) return;
    int start = (node == 0) ? 0 : g_rowoff[node - 1];
    int end = g_rowoff[node];
    const float4* X4 = (const float4*)xn;
    float e1 = 1.0f + epsArr[layer];
    float4 self = X4[(size_t)node * 32 + lane];
    float ax = self.x * e1, ay = self.y * e1, az = self.z * e1, aw = self.w * e1;
    int e = start;
    for (; e + 4 <= end; e += 4) {
        int s0 = g_sorted_src[e];
        int s1 = g_sorted_src[e + 1];
        int s2 = g_sorted_src[e + 2];
        int s3 = g_sorted_src[e + 3];
        float4 v0 = X4[(size_t)s0 * 32 + lane];
        float4 v1 = X4[(size_t)s1 * 32 + lane];
        float4 v2 = X4[(size_t)s2 * 32 + lane];
        float4 v3 = X4[(size_t)s3 * 32 + lane];
        ax += v0.x + v1.x + v2.x + v3.x;
        ay += v0.y + v1.y + v2.y + v3.y;
        az += v0.z + v1.z + v2.z + v3.z;
        aw += v0.w + v1.w + v2.w + v3.w;
    }
    for (; e < end; e++) {
        int s0 = g_sorted_src[e];
        float4 v0 = X4[(size_t)s0 * 32 + lane];
        ax += v0.x; ay += v0.y; az += v0.z; aw += v0.w;
    }
    ((float4*)agg)[(size_t)node * 32 + lane] = make_float4(ax, ay, az, aw);
}

// GEMM: out[n,128] = act(A)[n,128] @ W[128,128] + bias
// applyBN: BN params computed inline from statsIn + gamma/beta, fused on A load.
// statsOut != nullptr: per-column sum/sumsq of output accumulated into it.
__global__ __launch_bounds__(256, 1)
void gemm_kernel(const float* __restrict__ A,
                 const float* __restrict__ W,
                 const float* __restrict__ bias,
                 float* __restrict__ out,
                 int n, int applyBN,
                 const float* __restrict__ statsIn,
                 const float* __restrict__ gamma,
                 const float* __restrict__ beta,
                 float* __restrict__ statsOut,
                 float invN) {
    extern __shared__ float smem[];
    float* ws = smem;
    float* xs = smem + 16384;
    float4* ws4 = (float4*)ws;
    float4* xs4 = (float4*)xs;
    __shared__ __align__(16) float bnsc[128], bnsh[128];

    int tid = threadIdx.x;
    int tx = tid & 15;
    int ty = tid >> 4;
    int rowBase = blockIdx.x << 7;

    if (applyBN) {
        if (tid < 128) {
            float mean = statsIn[tid] * invN;
            float var = statsIn[128 + tid] * invN - mean * mean;
            float scv = gamma[tid] * rsqrtf(fmaxf(var, 0.0f) + 1e-5f);
            bnsc[tid] = scv;
            bnsh[tid] = beta[tid] - mean * scv;
        }
        __syncthreads();
    }

    const float4* W4 = (const float4*)W;
#pragma unroll
    for (int i = 0; i < 16; i++) ws4[tid + 256 * i] = W4[tid + 256 * i];

    const float4* A4 = (const float4*)A;
#pragma unroll
    for (int i = 0; i < 16; i++) {
        int li = tid + 256 * i;
        int r = li >> 5;
        int c4 = li & 31;
        int grow = rowBase + r;
        float4 v = make_float4(0.f, 0.f, 0.f, 0.f);
        if (grow < n) v = A4[(size_t)grow * 32 + c4];
        if (applyBN) {
            float4 s = ((const float4*)bnsc)[c4];
            float4 t = ((const float4*)bnsh)[c4];
            v.x = fmaxf(fmaf(v.x, s.x, t.x), 0.0f);
            v.y = fmaxf(fmaf(v.y, s.y, t.y), 0.0f);
            v.z = fmaxf(fmaf(v.z, s.z, t.z), 0.0f);
            v.w = fmaxf(fmaf(v.w, s.w, t.w), 0.0f);
        }
        xs4[li] = v;
    }
    __syncthreads();

    unsigned long long acc2[8][4];
#pragma unroll
    for (int r = 0; r < 8; r++)
#pragma unroll
        for (int c = 0; c < 4; c++) acc2[r][c] = 0ull;

#pragma unroll 2
    for (int k = 0; k < 128; k += 4) {
        float a[8][4];
#pragma unroll
        for (int r = 0; r < 8; r++) {
            float4 av = xs4[(ty * 8 + r) * 32 + (k >> 2)];
            a[r][0] = av.x; a[r][1] = av.y; a[r][2] = av.z; a[r][3] = av.w;
        }
#pragma unroll
        for (int kk = 0; kk < 4; kk++) {
            float4 w0 = ws4[(k + kk) * 32 + tx];
            float4 w1 = ws4[(k + kk) * 32 + tx + 16];
            unsigned long long w2[4];
            asm("mov.b64 %0, {%1, %2};" : "=l"(w2[0]) : "f"(w0.x), "f"(w0.y));
            asm("mov.b64 %0, {%1, %2};" : "=l"(w2[1]) : "f"(w0.z), "f"(w0.w));
            asm("mov.b64 %0, {%1, %2};" : "=l"(w2[2]) : "f"(w1.x), "f"(w1.y));
            asm("mov.b64 %0, {%1, %2};" : "=l"(w2[3]) : "f"(w1.z), "f"(w1.w));
#pragma unroll
            for (int r = 0; r < 8; r++) {
                unsigned long long a2;
                asm("mov.b64 %0, {%1, %1};" : "=l"(a2) : "f"(a[r][kk]));
#pragma unroll
                for (int c = 0; c < 4; c++)
                    asm("fma.rn.f32x2 %0, %1, %2, %0;"
                        : "+l"(acc2[r][c]) : "l"(a2), "l"(w2[c]));
            }
        }
    }

    float4 b0 = ((const float4*)bias)[tx];
    float4 b1v = ((const float4*)bias)[tx + 16];
    float bv[8] = {b0.x, b0.y, b0.z, b0.w, b1v.x, b1v.y, b1v.z, b1v.w};

    float psum[8], psq[8];
#pragma unroll
    for (int c = 0; c < 8; c++) { psum[c] = 0.0f; psq[c] = 0.0f; }

    int doStats = (statsOut != nullptr);

#pragma unroll
    for (int r = 0; r < 8; r++) {
        int grow = rowBase + ty * 8 + r;
        if (grow < n) {
            float o[8];
#pragma unroll
            for (int c = 0; c < 4; c++) {
                float lo, hi;
                asm("mov.b64 {%0, %1}, %2;" : "=f"(lo), "=f"(hi) : "l"(acc2[r][c]));
                o[2 * c] = lo + bv[2 * c];
                o[2 * c + 1] = hi + bv[2 * c + 1];
            }
            ((float4*)out)[(size_t)grow * 32 + tx] = make_float4(o[0], o[1], o[2], o[3]);
            ((float4*)out)[(size_t)grow * 32 + tx + 16] = make_float4(o[4], o[5], o[6], o[7]);
            if (doStats) {
#pragma unroll
                for (int c = 0; c < 8; c++) {
                    psum[c] += o[c];
                    psq[c] += o[c] * o[c];
                }
            }
        }
    }

    if (doStats) {
        __syncthreads();
        float* redS = ws;
        float* redQ = ws + 2048;
        ((float4*)&redS[ty * 128])[tx]      = make_float4(psum[0], psum[1], psum[2], psum[3]);
        ((float4*)&redS[ty * 128])[tx + 16] = make_float4(psum[4], psum[5], psum[6], psum[7]);
        ((float4*)&redQ[ty * 128])[tx]      = make_float4(psq[0], psq[1], psq[2], psq[3]);
        ((float4*)&redQ[ty * 128])[tx + 16] = make_float4(psq[4], psq[5], psq[6], psq[7]);
        __syncthreads();
        if (tid < 128) {
            float sv = 0.0f;
#pragma unroll
            for (int t = 0; t < 16; t++) sv += redS[t * 128 + tid];
            atomicAdd(&statsOut[tid], sv);
        } else {
            int c = tid - 128;
            float q = 0.0f;
#pragma unroll
            for (int t = 0; t < 16; t++) q += redQ[t * 128 + c];
            atomicAdd(&statsOut[128 + c], q);
        }
    }
}

extern "C" void kernel_launch(void* const* d_in, const int* in_sizes, int n_in,
                              void* d_out, int out_size) {
    const float* x     = (const float*)d_in[0];
    const void*  ei    = d_in[1];
    const float* eps   = (const float*)d_in[2];
    const float* W1    = (const float*)d_in[3];
    const float* b1    = (const float*)d_in[4];
    const float* g1    = (const float*)d_in[5];
    const float* beta1 = (const float*)d_in[6];
    const float* W2    = (const float*)d_in[7];
    const float* b2    = (const float*)d_in[8];
    const float* bng   = (const float*)d_in[9];
    const float* bnb   = (const float*)d_in[10];
    float* out = (float*)d_out;

    int n = in_sizes[0] / DD;
    int E = in_sizes[1] / 2;

    float* bufs = nullptr;
    cudaGetSymbolAddress((void**)&bufs, g_bufs);
    float* xn   = bufs;
    float* aggb = bufs + (size_t)1 * NMAX * DD;
    float* h    = bufs + (size_t)2 * NMAX * DD;
    float* xraw = bufs + (size_t)3 * NMAX * DD;

    float* stats = nullptr;
    cudaGetSymbolAddress((void**)&stats, g_stats);

    cudaFuncSetAttribute((const void*)gemm_kernel,
                         cudaFuncAttributeMaxDynamicSharedMemorySize, GEMM_SMEM_BYTES);

    int nb256 = (n + 255) / 256;
    int edgeBlocks = (E + 8 * 256 - 1) / (8 * 256);

    setup_kernel<<<nb256, 256>>>((const int*)ei, n);
    hist_kernel<<<edgeBlocks, 256>>>(ei, E);
    scan_kernel<<<nb256, 256>>>(n);
    place_kernel<<<edgeBlocks, 256>>>(ei, E);

    int prepBlocks = (n * (DD / 4) + 255) / 256;
    int aggBlocks = (n + 7) / 8;           // 8 warps/block, 1 node/warp
    int gemmBlocks = (n + 127) / 128;
    float invN = 1.0f / (float)n;

    for (int layer = 0; layer < 3; layer++) {
        const float* cur = (layer == 0) ? x : xn;
        if (layer > 0) {
            // BN+ReLU from previous layer's output stats (slot 2*(layer-1)+1)
            prep_kernel<<<prepBlocks, 256>>>(
                xraw, xn, stats + (size_t)(2 * (layer - 1) + 1) * 256,
                bng + (layer - 1) * DD, bnb + (layer - 1) * DD, invN, n);
        }
        agg_kernel<<<aggBlocks, 256>>>(cur, aggb, eps, layer, n);
        // GEMM1: no BN in, stats -> slot 2*layer
        gemm_kernel<<<gemmBlocks, 256, GEMM_SMEM_BYTES>>>(
            aggb, W1 + (size_t)layer * DD * DD, b1 + layer * DD, h, n,
            0, nullptr, nullptr, nullptr,
            stats + (size_t)(2 * layer) * 256, invN);
        int last = (layer == 2);
        float* o = last ? out : xraw;
        // GEMM2: BN in from slot 2*layer (g1/beta1), stats -> slot 2*layer+1
        gemm_kernel<<<gemmBlocks, 256, GEMM_SMEM_BYTES>>>(
            h, W2 + (size_t)layer * DD * DD, b2 + layer * DD, o, n,
            1, stats + (size_t)(2 * layer) * 256,
            g1 + layer * DD, beta1 + layer * DD,
            last ? nullptr : stats + (size_t)(2 * layer + 1) * 256, invN);
    }
}

// round 14
// speedup vs baseline: 1.7244x; 1.5213x over previous
#include <cuda_runtime.h>
#include <cstdint>

// Problem constants (shape-fixed per problem instance)
#define DD    128
#define NMAX  50000
#define EMAX  800000
#define GEMM_SMEM_FLOATS (16384 + 16384)
#define GEMM_SMEM_BYTES  (GEMM_SMEM_FLOATS * 4)

// -------- scratch (allocation-free: __device__ globals) --------
__device__ float g_bufs[4ull * NMAX * DD];  // xn, agg, h, xraw
// [0:128) colsum  [128:256) colsumsq  [256:384) bn scale  [384:512) bn shift
__device__ __align__(16) float g_small[512];
__device__ int g_edge64;
// CSR scratch
__device__ int g_sorted_src[EMAX];
__device__ int g_rowoff[NMAX + 1];   // becomes END offsets after placement
__device__ int g_counts[NMAX];
__device__ int g_partials[1024];

// -------- setup: zero counts + zero stats + parallel dtype detect --------
__global__ void setup_kernel(const int* __restrict__ ei, int n) {
    int i = blockIdx.x * 256 + threadIdx.x;
    if (i < n) g_counts[i] = 0;
    if (blockIdx.x == 0) {
        int t = threadIdx.x;
        g_small[t] = 0.0f;               // zero colsum + colsumsq
        __shared__ int ok;
        if (t == 0) ok = 1;
        __syncthreads();
        // int64 node ids < 2^31 -> every odd int32 word is zero
        if (ei[2 * t + 1] != 0) atomicExch(&ok, 0);
        __syncthreads();
        if (t == 0) g_edge64 = ok;
    }
}

// ---- counting sort of edges by dst (built once per launch) ----
__global__ void hist_kernel(const void* __restrict__ ei, int E) {
    int base = blockIdx.x * blockDim.x + threadIdx.x;
    int stride = gridDim.x * blockDim.x;
    if (g_edge64) {
        const long long* dstp = (const long long*)ei + E;
        for (int e = base; e < E; e += stride)
            atomicAdd(&g_counts[(int)dstp[e]], 1);
    } else {
        const int* dstp = (const int*)ei + E;
        for (int e = base; e < E; e += stride)
            atomicAdd(&g_counts[dstp[e]], 1);
    }
}

// block-local exclusive scan of counts -> g_rowoff; block sums -> g_partials
__global__ void scanA_kernel(int n) {
    __shared__ int sm[256];
    int t = threadIdx.x;
    int i = blockIdx.x * 256 + t;
    int v = (i < n) ? g_counts[i] : 0;
    sm[t] = v;
    __syncthreads();
#pragma unroll
    for (int off = 1; off < 256; off <<= 1) {
        int add = (t >= off) ? sm[t - off] : 0;
        __syncthreads();
        sm[t] += add;
        __syncthreads();
    }
    if (i < n) g_rowoff[i] = sm[t] - v;       // exclusive, block-local
    if (t == 255) g_partials[blockIdx.x] = sm[t];
}

// exclusive scan of block partials (nb <= 256), single block of 256
__global__ void scanB_kernel(int nb) {
    __shared__ int sm[256];
    int t = threadIdx.x;
    int v = (t < nb) ? g_partials[t] : 0;
    sm[t] = v;
    __syncthreads();
#pragma unroll
    for (int off = 1; off < 256; off <<= 1) {
        int add = (t >= off) ? sm[t - off] : 0;
        __syncthreads();
        sm[t] += add;
        __syncthreads();
    }
    if (t < nb) g_partials[t] = sm[t] - v;    // exclusive
}

__global__ void scanC2_kernel(int n) {
    int i = blockIdx.x * 256 + threadIdx.x;
    if (i < n) g_rowoff[i] += g_partials[blockIdx.x];
}

// place edges: pos = old rowoff cursor; rowoff becomes END offsets afterwards
__global__ void place_kernel(const void* __restrict__ ei, int E) {
    int base = blockIdx.x * blockDim.x + threadIdx.x;
    int stride = gridDim.x * blockDim.x;
    if (g_edge64) {
        const long long* e64 = (const long long*)ei;
        for (int e = base; e < E; e += stride) {
            int s = (int)e64[e];
            int d = (int)e64[E + e];
            g_sorted_src[atomicAdd(&g_rowoff[d], 1)] = s;
        }
    } else {
        const int* e32 = (const int*)ei;
        for (int e = base; e < E; e += stride) {
            int s = e32[e];
            int d = e32[E + e];
            g_sorted_src[atomicAdd(&g_rowoff[d], 1)] = s;
        }
    }
}

// prep: xn = BN+ReLU(raw) for layers > 0 (layer 0 uses x directly)
__global__ void prep_kernel(const float* __restrict__ raw,
                            float* __restrict__ xn, int n) {
    int idx = blockIdx.x * blockDim.x + threadIdx.x;
    int total = n * (DD / 4);
    if (idx >= total) return;
    float4 v = ((const float4*)raw)[idx];
    int c4 = idx & 31;
    float4 s = ((const float4*)(g_small + 256))[c4];
    float4 t = ((const float4*)(g_small + 384))[c4];
    v.x = fmaxf(fmaf(v.x, s.x, t.x), 0.0f);
    v.y = fmaxf(fmaf(v.y, s.y, t.y), 0.0f);
    v.z = fmaxf(fmaf(v.z, s.z, t.z), 0.0f);
    v.w = fmaxf(fmaf(v.w, s.w, t.w), 0.0f);
    ((float4*)xn)[idx] = v;
}

// gather aggregation: one warp per dst node; 8-deep gather pipeline (MLP=8).
// agg[i] = (1+eps)*xn[i] + sum_{e in CSR row i} xn[src[e]]
__global__ void agg_kernel(const float* __restrict__ xn,
                           float* __restrict__ agg,
                           const float* __restrict__ epsArr,
                           int layer, int n) {
    int node = (blockIdx.x * blockDim.x + threadIdx.x) >> 5;
    int lane = threadIdx.x & 31;
    if (node >= n) return;
    int start = (node == 0) ? 0 : g_rowoff[node - 1];
    int end = g_rowoff[node];
    const float4* X4 = (const float4*)xn;
    float e1 = 1.0f + epsArr[layer];
    float4 self = X4[(size_t)node * 32 + lane];
    float ax = self.x * e1, ay = self.y * e1, az = self.z * e1, aw = self.w * e1;
    int e = start;
    for (; e + 8 <= end; e += 8) {
        int si[8];
#pragma unroll
        for (int j = 0; j < 8; j++) si[j] = g_sorted_src[e + j];
        float4 v[8];
#pragma unroll
        for (int j = 0; j < 8; j++) v[j] = X4[(size_t)si[j] * 32 + lane];
        float sx0 = v[0].x + v[1].x, sx1 = v[2].x + v[3].x;
        float sx2 = v[4].x + v[5].x, sx3 = v[6].x + v[7].x;
        float sy0 = v[0].y + v[1].y, sy1 = v[2].y + v[3].y;
        float sy2 = v[4].y + v[5].y, sy3 = v[6].y + v[7].y;
        float sz0 = v[0].z + v[1].z, sz1 = v[2].z + v[3].z;
        float sz2 = v[4].z + v[5].z, sz3 = v[6].z + v[7].z;
        float sw0 = v[0].w + v[1].w, sw1 = v[2].w + v[3].w;
        float sw2 = v[4].w + v[5].w, sw3 = v[6].w + v[7].w;
        ax += (sx0 + sx1) + (sx2 + sx3);
        ay += (sy0 + sy1) + (sy2 + sy3);
        az += (sz0 + sz1) + (sz2 + sz3);
        aw += (sw0 + sw1) + (sw2 + sw3);
    }
    if (e + 4 <= end) {
        int s0 = g_sorted_src[e];
        int s1 = g_sorted_src[e + 1];
        int s2 = g_sorted_src[e + 2];
        int s3 = g_sorted_src[e + 3];
        float4 v0 = X4[(size_t)s0 * 32 + lane];
        float4 v1 = X4[(size_t)s1 * 32 + lane];
        float4 v2 = X4[(size_t)s2 * 32 + lane];
        float4 v3 = X4[(size_t)s3 * 32 + lane];
        ax += v0.x + v1.x + v2.x + v3.x;
        ay += v0.y + v1.y + v2.y + v3.y;
        az += v0.z + v1.z + v2.z + v3.z;
        aw += v0.w + v1.w + v2.w + v3.w;
        e += 4;
    }
    for (; e < end; e++) {
        int s0 = g_sorted_src[e];
        float4 v0 = X4[(size_t)s0 * 32 + lane];
        ax += v0.x; ay += v0.y; az += v0.z; aw += v0.w;
    }
    ((float4*)agg)[(size_t)node * 32 + lane] = make_float4(ax, ay, az, aw);
}

// GEMM: out[n,128] = act(A)[n,128] @ W[128,128] + bias
// Inner loop uses Blackwell packed fp32 FMA (fma.rn.f32x2); BN fused on load,
// per-column stats fused in epilogue.  (Byte-identical to the R9 version.)
__global__ __launch_bounds__(256, 1)
void gemm_kernel(const float* __restrict__ A,
                 const float* __restrict__ W,
                 const float* __restrict__ bias,
                 float* __restrict__ out,
                 int n, int applyBN, int accumStats) {
    extern __shared__ float smem[];
    float* ws = smem;
    float* xs = smem + 16384;
    float4* ws4 = (float4*)ws;
    float4* xs4 = (float4*)xs;

    int tid = threadIdx.x;
    int tx = tid & 15;
    int ty = tid >> 4;
    int rowBase = blockIdx.x << 7;

    const float4* W4 = (const float4*)W;
#pragma unroll
    for (int i = 0; i < 16; i++) ws4[tid + 256 * i] = W4[tid + 256 * i];

    const float4* A4 = (const float4*)A;
#pragma unroll
    for (int i = 0; i < 16; i++) {
        int li = tid + 256 * i;
        int r = li >> 5;
        int c4 = li & 31;
        int grow = rowBase + r;
        float4 v = make_float4(0.f, 0.f, 0.f, 0.f);
        if (grow < n) v = A4[(size_t)grow * 32 + c4];
        if (applyBN) {
            float4 s = ((const float4*)(g_small + 256))[c4];
            float4 t = ((const float4*)(g_small + 384))[c4];
            v.x = fmaxf(fmaf(v.x, s.x, t.x), 0.0f);
            v.y = fmaxf(fmaf(v.y, s.y, t.y), 0.0f);
            v.z = fmaxf(fmaf(v.z, s.z, t.z), 0.0f);
            v.w = fmaxf(fmaf(v.w, s.w, t.w), 0.0f);
        }
        xs4[li] = v;
    }
    __syncthreads();

    unsigned long long acc2[8][4];
#pragma unroll
    for (int r = 0; r < 8; r++)
#pragma unroll
        for (int c = 0; c < 4; c++) acc2[r][c] = 0ull;

#pragma unroll 2
    for (int k = 0; k < 128; k += 4) {
        float a[8][4];
#pragma unroll
        for (int r = 0; r < 8; r++) {
            float4 av = xs4[(ty * 8 + r) * 32 + (k >> 2)];
            a[r][0] = av.x; a[r][1] = av.y; a[r][2] = av.z; a[r][3] = av.w;
        }
#pragma unroll
        for (int kk = 0; kk < 4; kk++) {
            float4 w0 = ws4[(k + kk) * 32 + tx];
            float4 w1 = ws4[(k + kk) * 32 + tx + 16];
            unsigned long long w2[4];
            asm("mov.b64 %0, {%1, %2};" : "=l"(w2[0]) : "f"(w0.x), "f"(w0.y));
            asm("mov.b64 %0, {%1, %2};" : "=l"(w2[1]) : "f"(w0.z), "f"(w0.w));
            asm("mov.b64 %0, {%1, %2};" : "=l"(w2[2]) : "f"(w1.x), "f"(w1.y));
            asm("mov.b64 %0, {%1, %2};" : "=l"(w2[3]) : "f"(w1.z), "f"(w1.w));
#pragma unroll
            for (int r = 0; r < 8; r++) {
                unsigned long long a2;
                asm("mov.b64 %0, {%1, %1};" : "=l"(a2) : "f"(a[r][kk]));
#pragma unroll
                for (int c = 0; c < 4; c++)
                    asm("fma.rn.f32x2 %0, %1, %2, %0;"
                        : "+l"(acc2[r][c]) : "l"(a2), "l"(w2[c]));
            }
        }
    }

    float4 b0 = ((const float4*)bias)[tx];
    float4 b1v = ((const float4*)bias)[tx + 16];
    float bv[8] = {b0.x, b0.y, b0.z, b0.w, b1v.x, b1v.y, b1v.z, b1v.w};

    float psum[8], psq[8];
#pragma unroll
    for (int c = 0; c < 8; c++) { psum[c] = 0.0f; psq[c] = 0.0f; }

#pragma unroll
    for (int r = 0; r < 8; r++) {
        int grow = rowBase + ty * 8 + r;
        if (grow < n) {
            float o[8];
#pragma unroll
            for (int c = 0; c < 4; c++) {
                float lo, hi;
                asm("mov.b64 {%0, %1}, %2;" : "=f"(lo), "=f"(hi) : "l"(acc2[r][c]));
                o[2 * c] = lo + bv[2 * c];
                o[2 * c + 1] = hi + bv[2 * c + 1];
            }
            ((float4*)out)[(size_t)grow * 32 + tx] = make_float4(o[0], o[1], o[2], o[3]);
            ((float4*)out)[(size_t)grow * 32 + tx + 16] = make_float4(o[4], o[5], o[6], o[7]);
            if (accumStats) {
#pragma unroll
                for (int c = 0; c < 8; c++) {
                    psum[c] += o[c];
                    psq[c] += o[c] * o[c];
                }
            }
        }
    }

    if (accumStats) {
        __syncthreads();
        float* redS = ws;
        float* redQ = ws + 2048;
        ((float4*)&redS[ty * 128])[tx]      = make_float4(psum[0], psum[1], psum[2], psum[3]);
        ((float4*)&redS[ty * 128])[tx + 16] = make_float4(psum[4], psum[5], psum[6], psum[7]);
        ((float4*)&redQ[ty * 128])[tx]      = make_float4(psq[0], psq[1], psq[2], psq[3]);
        ((float4*)&redQ[ty * 128])[tx + 16] = make_float4(psq[4], psq[5], psq[6], psq[7]);
        __syncthreads();
        if (tid < 128) {
            float sv = 0.0f;
#pragma unroll
            for (int t = 0; t < 16; t++) sv += redS[t * 128 + tid];
            atomicAdd(&g_small[tid], sv);
        } else {
            int c = tid - 128;
            float q = 0.0f;
#pragma unroll
            for (int t = 0; t < 16; t++) q += redQ[t * 128 + c];
            atomicAdd(&g_small[128 + c], q);
        }
    }
}

__global__ void bnparams_kernel(const float* __restrict__ gamma,
                                const float* __restrict__ beta,
                                float invN) {
    int c = threadIdx.x;
    float mean = g_small[c] * invN;
    float var = g_small[128 + c] * invN - mean * mean;
    float sc = gamma[c] * rsqrtf(fmaxf(var, 0.0f) + 1e-5f);
    g_small[256 + c] = sc;
    g_small[384 + c] = beta[c] - mean * sc;
    g_small[c] = 0.0f;
    g_small[128 + c] = 0.0f;
}

extern "C" void kernel_launch(void* const* d_in, const int* in_sizes, int n_in,
                              void* d_out, int out_size) {
    const float* x     = (const float*)d_in[0];
    const void*  ei    = d_in[1];
    const float* eps   = (const float*)d_in[2];
    const float* W1    = (const float*)d_in[3];
    const float* b1    = (const float*)d_in[4];
    const float* g1    = (const float*)d_in[5];
    const float* beta1 = (const float*)d_in[6];
    const float* W2    = (const float*)d_in[7];
    const float* b2    = (const float*)d_in[8];
    const float* bng   = (const float*)d_in[9];
    const float* bnb   = (const float*)d_in[10];
    float* out = (float*)d_out;

    int n = in_sizes[0] / DD;
    int E = in_sizes[1] / 2;

    float* bufs = nullptr;
    cudaGetSymbolAddress((void**)&bufs, g_bufs);
    float* xn   = bufs;
    float* aggb = bufs + (size_t)1 * NMAX * DD;
    float* h    = bufs + (size_t)2 * NMAX * DD;
    float* xraw = bufs + (size_t)3 * NMAX * DD;

    cudaFuncSetAttribute((const void*)gemm_kernel,
                         cudaFuncAttributeMaxDynamicSharedMemorySize, GEMM_SMEM_BYTES);

    int nb256 = (n + 255) / 256;
    int edgeBlocks = (E + 8 * 256 - 1) / (8 * 256);   // ~8 edges/thread

    // --- one-time per launch: setup (zeros + dtype detect), CSR build ---
    setup_kernel<<<nb256, 256>>>((const int*)ei, n);
    hist_kernel<<<edgeBlocks, 256>>>(ei, E);
    scanA_kernel<<<nb256, 256>>>(n);
    scanB_kernel<<<1, 256>>>(nb256);
    scanC2_kernel<<<nb256, 256>>>(n);
    place_kernel<<<edgeBlocks, 256>>>(ei, E);

    int prepBlocks = (n * (DD / 4) + 255) / 256;
    int aggBlocks = (n + 7) / 8;           // 8 warps/block, 1 node/warp
    int gemmBlocks = (n + 127) / 128;
    float invN = 1.0f / (float)n;

    for (int layer = 0; layer < 3; layer++) {
        const float* cur = (layer == 0) ? x : xn;
        if (layer > 0) prep_kernel<<<prepBlocks, 256>>>(xraw, xn, n);
        agg_kernel<<<aggBlocks, 256>>>(cur, aggb, eps, layer, n);
        gemm_kernel<<<gemmBlocks, 256, GEMM_SMEM_BYTES>>>(
            aggb, W1 + (size_t)layer * DD * DD, b1 + layer * DD, h, n, 0, 1);
        bnparams_kernel<<<1, 128>>>(g1 + layer * DD, beta1 + layer * DD, invN);
        int last = (layer == 2);
        float* o = last ? out : xraw;
        gemm_kernel<<<gemmBlocks, 256, GEMM_SMEM_BYTES>>>(
            h, W2 + (size_t)layer * DD * DD, b2 + layer * DD, o, n, 1, last ? 0 : 1);
        if (!last)
            bnparams_kernel<<<1, 128>>>(bng + layer * DD, bnb + layer * DD, invN);
    }
}